// round 1
// baseline (speedup 1.0000x reference)
#include <cuda_runtime.h>
#include <cuda_bf16.h>
#include <math.h>

// Problem constants
#define B_   256
#define A_   64
#define G_   978
#define DDRUG 128
#define DCELL 50
#define DDOSE 128
#define CELLIN 978
#define DOSEIN 12
#define GLOBAL_ 306   // 128+50+128
#define EXPIN 434
#define E_   4
#define H_   128      // expert hidden

// -------- device scratch (no allocations allowed) --------
__device__ float d_gfeat[B_ * GLOBAL_];
__device__ float d_c1[B_ * 200];
__device__ float d_c2[B_ * 100];
__device__ float d_d1[B_ * 64];
__device__ float d_U[B_ * E_ * H_];      // [b][e][h]
__device__ float d_V[G_ * E_ * H_];      // [g][e][h]
__device__ int   d_eidx[B_ * 2];
__device__ float d_gw[B_ * 2];
__device__ float d_biasc[B_];

// ---------------------------------------------------------
// Generic linear (+bias, optional relu) kernel.
// Block handles RB batch rows; thread t = output column (t<N active).
// X assumed row-major [B,K]; W row-major [K,N]; Y[(r)*ldy + t].
// B must be a multiple of RB (true here: 256 % 32 == 0).
// ---------------------------------------------------------
template<int RB, int KC>
__global__ void linear_kernel(const float* __restrict__ X,
                              const float* __restrict__ W,
                              const float* __restrict__ bias,
                              float* __restrict__ Y, int ldy,
                              float* __restrict__ Y2,
                              int K, int N, int doRelu)
{
    __shared__ float sA[RB * KC];
    const int r0 = blockIdx.x * RB;
    const int t  = threadIdx.x;

    float acc[RB];
#pragma unroll
    for (int r = 0; r < RB; r++) acc[r] = 0.f;

    for (int k0 = 0; k0 < K; k0 += KC) {
        const int kc = (K - k0) < KC ? (K - k0) : KC;
        __syncthreads();
        for (int i = t; i < RB * kc; i += blockDim.x) {
            int r = i / kc, k = i - r * kc;
            sA[r * KC + k] = X[(r0 + r) * K + k0 + k];
        }
        __syncthreads();
        if (t < N) {
            for (int k = 0; k < kc; k++) {
                float w = W[(k0 + k) * N + t];
#pragma unroll
                for (int r = 0; r < RB; r++)
                    acc[r] = fmaf(sA[r * KC + k], w, acc[r]);
            }
        }
    }
    if (t < N) {
        float bb = bias[t];
#pragma unroll
        for (int r = 0; r < RB; r++) {
            float v = acc[r] + bb;
            if (doRelu) v = fmaxf(v, 0.f);
            Y[(r0 + r) * ldy + t] = v;
            if (Y2) Y2[(r0 + r) * N + t] = v;
        }
    }
}

// ---------------------------------------------------------
// Drug atom-sum: g[:, 0:128] = sum_a drug_atom_embed[b,a,:]
// ---------------------------------------------------------
__global__ void drug_kernel(const float* __restrict__ drug)
{
    int b = blockIdx.x;
    int d = threadIdx.x;     // 128 threads
    const float* p = drug + (size_t)b * A_ * DDRUG + d;
    float s = 0.f;
#pragma unroll
    for (int a = 0; a < A_; a++) s += p[a * DDRUG];
    d_gfeat[b * GLOBAL_ + d] = s;
}

// ---------------------------------------------------------
// Gating: hidden = relu(g@W1+b1), logits = hidden@W2+b2,
// top-2 softmax -> expert indices/weights + fused bias const.
// Block: 16 batch rows, 128 threads.
// ---------------------------------------------------------
__global__ void gate_kernel(const float* __restrict__ gateW1,
                            const float* __restrict__ gateb1,
                            const float* __restrict__ gateW2,
                            const float* __restrict__ gateb2,
                            const float* __restrict__ expb2)
{
    constexpr int RB = 16;
    __shared__ float sG[RB * GLOBAL_];
    __shared__ float sH[RB * 128];
    __shared__ float sL[RB * 4];
    const int b0 = blockIdx.x * RB;
    const int t  = threadIdx.x;  // 128

    for (int i = t; i < RB * GLOBAL_; i += blockDim.x) {
        int r = i / GLOBAL_, k = i - r * GLOBAL_;
        sG[r * GLOBAL_ + k] = d_gfeat[(b0 + r) * GLOBAL_ + k];
    }
    __syncthreads();

    {
        float acc[RB];
#pragma unroll
        for (int r = 0; r < RB; r++) acc[r] = 0.f;
        for (int k = 0; k < GLOBAL_; k++) {
            float w = gateW1[k * 128 + t];
#pragma unroll
            for (int r = 0; r < RB; r++)
                acc[r] = fmaf(sG[r * GLOBAL_ + k], w, acc[r]);
        }
        float bb = gateb1[t];
#pragma unroll
        for (int r = 0; r < RB; r++)
            sH[r * 128 + t] = fmaxf(acc[r] + bb, 0.f);
    }
    __syncthreads();

    if (t < RB * 4) {
        int r = t >> 2, e = t & 3;
        float a = gateb2[e];
        for (int k = 0; k < 128; k++)
            a = fmaf(sH[r * 128 + k], gateW2[k * 4 + e], a);
        sL[r * 4 + e] = a;
    }
    __syncthreads();

    if (t < RB) {
        int b = b0 + t;
        float v[4];
#pragma unroll
        for (int j = 0; j < 4; j++) v[j] = sL[t * 4 + j];
        int i0 = 0;
#pragma unroll
        for (int j = 1; j < 4; j++) if (v[j] > v[i0]) i0 = j;
        int i1 = (i0 == 0) ? 1 : 0;
#pragma unroll
        for (int j = 0; j < 4; j++) if (j != i0 && v[j] > v[i1]) i1 = j;
        float m  = fmaxf(v[i0], v[i1]);
        float e0 = __expf(v[i0] - m), e1 = __expf(v[i1] - m);
        float inv = 1.f / (e0 + e1);
        float w0 = e0 * inv, w1 = e1 * inv;
        d_eidx[2 * b]     = i0;
        d_eidx[2 * b + 1] = i1;
        d_gw[2 * b]       = w0;
        d_gw[2 * b + 1]   = w1;
        d_biasc[b]        = w0 * expb2[i0] + w1 * expb2[i1];
    }
}

// ---------------------------------------------------------
// U / V precompute: Y[row][e*128+h] = sum_k X[row][k] * expW1[e][kOff+k][h] (+bias)
// 512 threads = (e,h); RB=32 rows per block.
// ---------------------------------------------------------
__global__ void uv_kernel(const float* __restrict__ X, int K,
                          const float* __restrict__ Wexp, int kOff,
                          const float* __restrict__ bias,
                          float* __restrict__ Y, int nRows)
{
    constexpr int RB = 32;
    __shared__ float sA[RB * GLOBAL_];   // max K = 306
    const int r0 = blockIdx.x * RB;
    const int t  = threadIdx.x;          // 512
    const int e  = t >> 7, h = t & 127;

    for (int i = t; i < RB * K; i += blockDim.x) {
        int r = i / K, k = i - r * K;
        sA[r * K + k] = (r0 + r < nRows) ? X[(r0 + r) * K + k] : 0.f;
    }
    __syncthreads();

    float acc[RB];
    float bb = bias ? bias[t] : 0.f;
#pragma unroll
    for (int r = 0; r < RB; r++) acc[r] = bb;

    const float* wp = Wexp + (size_t)e * EXPIN * H_ + (size_t)kOff * H_ + h;
    for (int k = 0; k < K; k++) {
        float w = wp[(size_t)k * H_];
#pragma unroll
        for (int r = 0; r < RB; r++)
            acc[r] = fmaf(sA[r * K + k], w, acc[r]);
    }
#pragma unroll
    for (int r = 0; r < RB; r++)
        if (r0 + r < nRows) Y[(r0 + r) * (E_ * H_) + t] = acc[r];
}

// ---------------------------------------------------------
// Combine: pred[b,g] = sum_{e in top2(b)} gw[e] * ( sum_h relu(U[b,e,h]+V[g,e,h]) * W2[e,h] ) + biasc[b]
// Block: 16 warps (one b each), 16-gene V tile in smem.
// Lane l owns h in [4l, 4l+4).
// ---------------------------------------------------------
__global__ void combine_kernel(const float* __restrict__ expW2,
                               float* __restrict__ pred)
{
    __shared__ float4 sV[16 * 128];      // 16 genes x (4e*128h)/4 float4 = 32KB
    __shared__ float  sOut[16][17];
    const int g0   = blockIdx.x * 16;
    const int warp = threadIdx.x >> 5;
    const int lane = threadIdx.x & 31;
    const int b    = blockIdx.y * 16 + warp;
    const int nG   = (G_ - g0) < 16 ? (G_ - g0) : 16;

    const float4* V4 = reinterpret_cast<const float4*>(d_V);
    for (int i = threadIdx.x; i < nG * 128; i += blockDim.x)
        sV[i] = V4[g0 * 128 + i];
    __syncthreads();

    const int   e0  = d_eidx[2 * b], e1 = d_eidx[2 * b + 1];
    const float gw0 = d_gw[2 * b],   gw1 = d_gw[2 * b + 1];
    const float bc  = d_biasc[b];

    const float4* U4 = reinterpret_cast<const float4*>(d_U) + b * 128;
    const float4 u0  = U4[e0 * 32 + lane];
    const float4 u1  = U4[e1 * 32 + lane];
    const float4* W4 = reinterpret_cast<const float4*>(expW2);
    const float4 w20 = W4[e0 * 32 + lane];
    const float4 w21 = W4[e1 * 32 + lane];

    for (int gi = 0; gi < nG; gi++) {
        float4 v = sV[gi * 128 + e0 * 32 + lane];
        float t0 =           fmaxf(u0.x + v.x, 0.f) * w20.x;
        t0 = fmaf(fmaxf(u0.y + v.y, 0.f), w20.y, t0);
        t0 = fmaf(fmaxf(u0.z + v.z, 0.f), w20.z, t0);
        t0 = fmaf(fmaxf(u0.w + v.w, 0.f), w20.w, t0);
        v = sV[gi * 128 + e1 * 32 + lane];
        float t1 =           fmaxf(u1.x + v.x, 0.f) * w21.x;
        t1 = fmaf(fmaxf(u1.y + v.y, 0.f), w21.y, t1);
        t1 = fmaf(fmaxf(u1.z + v.z, 0.f), w21.z, t1);
        t1 = fmaf(fmaxf(u1.w + v.w, 0.f), w21.w, t1);
        float p = gw0 * t0 + gw1 * t1;
#pragma unroll
        for (int o = 16; o; o >>= 1)
            p += __shfl_xor_sync(0xffffffffu, p, o);
        if (lane == 0) sOut[warp][gi] = p + bc;
    }
    __syncwarp();
    if (lane < nG)
        pred[b * G_ + g0 + lane] = sOut[warp][lane];
}

// ---------------------------------------------------------
extern "C" void kernel_launch(void* const* d_in, const int* in_sizes, int n_in,
                              void* d_out, int out_size)
{
    const float* drug_atom = (const float*)d_in[0];
    const float* gex       = (const float*)d_in[1];
    const float* idose     = (const float*)d_in[2];
    const float* cW1 = (const float*)d_in[3];  const float* cb1 = (const float*)d_in[4];
    const float* cW2 = (const float*)d_in[5];  const float* cb2 = (const float*)d_in[6];
    const float* cW3 = (const float*)d_in[7];  const float* cb3 = (const float*)d_in[8];
    const float* dW1 = (const float*)d_in[9];  const float* db1 = (const float*)d_in[10];
    const float* dW2 = (const float*)d_in[11]; const float* db2 = (const float*)d_in[12];
    const float* gene_emb = (const float*)d_in[13];
    const float* gW1 = (const float*)d_in[14]; const float* gb1 = (const float*)d_in[15];
    const float* gW2 = (const float*)d_in[16]; const float* gb2 = (const float*)d_in[17];
    const float* eW1 = (const float*)d_in[18]; const float* eb1 = (const float*)d_in[19];
    const float* eW2 = (const float*)d_in[20]; const float* eb2 = (const float*)d_in[21];

    float* pred = (float*)d_out;
    float* cellOut = (out_size >= B_ * G_ + B_ * DCELL) ? pred + B_ * G_ : nullptr;

    // resolve __device__ scratch addresses (host-side, capture-safe)
    float *p_gfeat, *p_c1, *p_c2, *p_d1, *p_U, *p_V;
    cudaGetSymbolAddress((void**)&p_gfeat, d_gfeat);
    cudaGetSymbolAddress((void**)&p_c1,    d_c1);
    cudaGetSymbolAddress((void**)&p_c2,    d_c2);
    cudaGetSymbolAddress((void**)&p_d1,    d_d1);
    cudaGetSymbolAddress((void**)&p_U,     d_U);
    cudaGetSymbolAddress((void**)&p_V,     d_V);

    // 1) drug sum -> gfeat[:, 0:128]
    drug_kernel<<<B_, 128>>>(drug_atom);

    // 2) cell encoder: 978 -> 200 -> 100 -> 50
    linear_kernel<32, 256><<<B_ / 32, 256>>>(gex, cW1, cb1, p_c1, 200, nullptr, CELLIN, 200, 1);
    linear_kernel<32, 256><<<B_ / 32, 128>>>(p_c1, cW2, cb2, p_c2, 100, nullptr, 200, 100, 1);
    linear_kernel<32, 256><<<B_ / 32, 64>>>(p_c2, cW3, cb3, p_gfeat + 128, GLOBAL_, cellOut, 100, DCELL, 1);

    // 3) dose encoder: 12 -> 64 -> 128
    linear_kernel<32, 256><<<B_ / 32, 64>>>(idose, dW1, db1, p_d1, 64, nullptr, DOSEIN, 64, 1);
    linear_kernel<32, 256><<<B_ / 32, 128>>>(p_d1, dW2, db2, p_gfeat + 178, GLOBAL_, nullptr, 64, DDOSE, 1);

    // 4) gating (top-2 softmax)
    gate_kernel<<<B_ / 16, 128>>>(gW1, gb1, gW2, gb2, eb2);

    // 5) U = g @ W1[:, :306, :] + b1     (per-batch part)
    uv_kernel<<<B_ / 32, 512>>>(p_gfeat, GLOBAL_, eW1, 0, eb1, p_U, B_);

    // 6) V = gene_emb @ W1[:, 306:, :]   (per-gene part)
    uv_kernel<<<(G_ + 31) / 32, 512>>>(gene_emb, H_, eW1, GLOBAL_, nullptr, p_V, G_);

    // 7) combine: top-2 expert mixture over genes
    dim3 cg((G_ + 15) / 16, B_ / 16);
    combine_kernel<<<cg, 512>>>(eW2, pred);
}

// round 2
// speedup vs baseline: 4.1303x; 4.1303x over previous
#include <cuda_runtime.h>
#include <cuda_bf16.h>
#include <math.h>

// Problem constants
#define B_   256
#define A_   64
#define G_   978
#define DDRUG 128
#define DCELL 50
#define DDOSE 128
#define CELLIN 978
#define DOSEIN 12
#define GLOBAL_ 306   // 128+50+128
#define EXPIN 434
#define E_   4
#define H_   128      // expert hidden

// -------- device scratch (no allocations allowed) --------
__device__ float d_gfeat[B_ * GLOBAL_];
__device__ float d_c1[B_ * 200];
__device__ float d_c2[B_ * 100];
__device__ float d_d1[B_ * 64];
__device__ float d_U[B_ * E_ * H_];      // [b][e*128+h]
__device__ float d_V[G_ * E_ * H_];      // [g][e*128+h]
__device__ int   d_eidx[B_ * 2];
__device__ float d_gw[B_ * 2];
__device__ float d_biasc[B_];

// ---------------------------------------------------------
// Shared-tile linear helper. Loads RB rows of X (padded stride Kp) into sA,
// then each active thread computes one output column via float4 broadcast
// shared reads (k unrolled by 4).
// ---------------------------------------------------------
template<int RB>
__device__ __forceinline__ void lin_tile(
    const float* __restrict__ X, int ldx, int K, int Kp, int nRows, int r0,
    const float* __restrict__ W, int ldw, int wcol,
    float b, bool active,
    float* __restrict__ Y, int ldy, int ycol,
    float* __restrict__ Y2, int ldy2, int y2col,
    bool doRelu, float* sA)
{
    const int tid = threadIdx.x, nt = blockDim.x;
    for (int i = tid; i < RB * Kp; i += nt) {
        int r = i / Kp, k = i - r * Kp;
        float v = 0.f;
        if (k < K && (r0 + r) < nRows) v = X[(r0 + r) * ldx + k];
        sA[i] = v;
    }
    __syncthreads();
    if (!active) return;

    float acc[RB];
#pragma unroll
    for (int r = 0; r < RB; r++) acc[r] = b;

    const int kmain = K & ~3;
    for (int k = 0; k < kmain; k += 4) {
        float w0 = W[(k + 0) * ldw + wcol];
        float w1 = W[(k + 1) * ldw + wcol];
        float w2 = W[(k + 2) * ldw + wcol];
        float w3 = W[(k + 3) * ldw + wcol];
#pragma unroll
        for (int r = 0; r < RB; r++) {
            float4 x = *reinterpret_cast<const float4*>(sA + r * Kp + k);
            acc[r] = fmaf(x.x, w0, acc[r]);
            acc[r] = fmaf(x.y, w1, acc[r]);
            acc[r] = fmaf(x.z, w2, acc[r]);
            acc[r] = fmaf(x.w, w3, acc[r]);
        }
    }
    for (int k = kmain; k < K; k++) {
        float w = W[k * ldw + wcol];
#pragma unroll
        for (int r = 0; r < RB; r++)
            acc[r] = fmaf(sA[r * Kp + k], w, acc[r]);
    }
#pragma unroll
    for (int r = 0; r < RB; r++) {
        if ((r0 + r) >= nRows) break;
        float v = doRelu ? fmaxf(acc[r], 0.f) : acc[r];
        Y[(r0 + r) * ldy + ycol] = v;
        if (Y2) Y2[(r0 + r) * ldy2 + y2col] = v;
    }
}

// ---------------------------------------------------------
// Stage A: all input-only stages fused via blockIdx partition.
//   [0,128)   drug atom-sum (2 rows/block)
//   [128,160) cell L1: 978->200 (8 rows/block)
//   [160,224) dose L1: 12->64  (4 rows/block, direct)
//   [224,470) V = gene_emb @ expW1[:,306:,:] (8 rows x 2 experts / block)
// ---------------------------------------------------------
__global__ void stageA(const float* __restrict__ drug,
                       const float* __restrict__ gex,
                       const float* __restrict__ cW1, const float* __restrict__ cb1,
                       const float* __restrict__ idose,
                       const float* __restrict__ dW1, const float* __restrict__ db1,
                       const float* __restrict__ gene_emb,
                       const float* __restrict__ eW1)
{
    __shared__ __align__(16) float sA[8 * 980];
    const int blk = blockIdx.x;
    const int t = threadIdx.x;   // 256

    if (blk < 128) {
        int b = blk * 2 + (t >> 7);
        int d = t & 127;
        const float* p = drug + (size_t)b * A_ * DDRUG + d;
        float s = 0.f;
#pragma unroll
        for (int a = 0; a < A_; a++) s += p[a * DDRUG];
        d_gfeat[b * GLOBAL_ + d] = s;
    } else if (blk < 160) {
        int r0 = (blk - 128) * 8;
        lin_tile<8>(gex, CELLIN, CELLIN, 980, B_, r0,
                    cW1, 200, t, (t < 200) ? cb1[t] : 0.f, t < 200,
                    d_c1, 200, t, nullptr, 0, 0, true, sA);
    } else if (blk < 224) {
        int row = (blk - 160) * 4 + (t >> 6);
        int col = t & 63;
        float a = db1[col];
        const float* x = idose + row * DOSEIN;
#pragma unroll
        for (int k = 0; k < DOSEIN; k++)
            a = fmaf(x[k], dW1[k * 64 + col], a);
        d_d1[row * 64 + col] = fmaxf(a, 0.f);
    } else {
        int idx = blk - 224;            // 0..245
        int rt = idx >> 1, ep = idx & 1;
        int r0 = rt * 8;
        int e = ep * 2 + (t >> 7), h = t & 127;
        const float* Wv = eW1 + (size_t)e * EXPIN * H_ + (size_t)GLOBAL_ * H_;
        lin_tile<8>(gene_emb, 128, 128, 128, G_, r0,
                    Wv, H_, h, 0.f, true,
                    d_V, E_ * H_, e * H_ + h, nullptr, 0, 0, false, sA);
    }
}

// ---------------------------------------------------------
// Stage B: cell L2 (200->100) + dose L2 (64->128) fused
//   [0,32) cellL2, [32,64) doseL2 ; 256 threads
// ---------------------------------------------------------
__global__ void stageB(const float* __restrict__ cW2, const float* __restrict__ cb2,
                       const float* __restrict__ dW2, const float* __restrict__ db2)
{
    __shared__ __align__(16) float sA[8 * 200];
    const int blk = blockIdx.x;
    const int t = threadIdx.x;

    if (blk < 32) {
        int r0 = blk * 8;
        lin_tile<8>(d_c1, 200, 200, 200, B_, r0,
                    cW2, 100, t, (t < 100) ? cb2[t] : 0.f, t < 100,
                    d_c2, 100, t, nullptr, 0, 0, true, sA);
    } else {
        int r0 = (blk - 32) * 8;
        lin_tile<8>(d_d1, 64, 64, 64, B_, r0,
                    dW2, 128, t, (t < 128) ? db2[t] : 0.f, t < 128,
                    d_gfeat, GLOBAL_, 178 + t, nullptr, 0, 0, true, sA);
    }
}

// ---------------------------------------------------------
// Stage C: cell L3 (100->50), writes gfeat[:,128:178] and cell output
// ---------------------------------------------------------
__global__ void stageC(const float* __restrict__ cW3, const float* __restrict__ cb3,
                       float* __restrict__ cellOut)
{
    __shared__ __align__(16) float sA[8 * 100];
    const int t = threadIdx.x;
    int r0 = blockIdx.x * 8;
    lin_tile<8>(d_c2, 100, 100, 100, B_, r0,
                cW3, 50, t, (t < 50) ? cb3[t] : 0.f, t < 50,
                d_gfeat, GLOBAL_, 128 + t, cellOut, 50, t, true, sA);
}

// ---------------------------------------------------------
// Stage D: gating. 8 rows/block, 128 threads, grid 32.
// ---------------------------------------------------------
__global__ void stageD(const float* __restrict__ gW1, const float* __restrict__ gb1,
                       const float* __restrict__ gW2, const float* __restrict__ gb2,
                       const float* __restrict__ expb2)
{
    __shared__ __align__(16) float sG[8 * 308];
    __shared__ float sH[8 * 128];
    __shared__ float sL[32];
    const int b0 = blockIdx.x * 8;
    const int t = threadIdx.x;   // 128

    for (int i = t; i < 8 * 308; i += 128) {
        int r = i / 308, k = i - r * 308;
        sG[i] = (k < GLOBAL_) ? d_gfeat[(b0 + r) * GLOBAL_ + k] : 0.f;
    }
    __syncthreads();

    {
        float acc[8];
#pragma unroll
        for (int r = 0; r < 8; r++) acc[r] = gb1[t];
        const int kmain = GLOBAL_ & ~3;   // 304
        for (int k = 0; k < kmain; k += 4) {
            float w0 = gW1[(k + 0) * 128 + t];
            float w1 = gW1[(k + 1) * 128 + t];
            float w2 = gW1[(k + 2) * 128 + t];
            float w3 = gW1[(k + 3) * 128 + t];
#pragma unroll
            for (int r = 0; r < 8; r++) {
                float4 x = *reinterpret_cast<const float4*>(sG + r * 308 + k);
                acc[r] = fmaf(x.x, w0, acc[r]);
                acc[r] = fmaf(x.y, w1, acc[r]);
                acc[r] = fmaf(x.z, w2, acc[r]);
                acc[r] = fmaf(x.w, w3, acc[r]);
            }
        }
        for (int k = kmain; k < GLOBAL_; k++) {
            float w = gW1[k * 128 + t];
#pragma unroll
            for (int r = 0; r < 8; r++)
                acc[r] = fmaf(sG[r * 308 + k], w, acc[r]);
        }
#pragma unroll
        for (int r = 0; r < 8; r++)
            sH[r * 128 + t] = fmaxf(acc[r], 0.f);
    }
    __syncthreads();

    if (t < 32) {
        int r = t >> 2, e = t & 3;
        float a = gb2[e];
        for (int k = 0; k < 128; k++)
            a = fmaf(sH[r * 128 + k], gW2[k * 4 + e], a);
        sL[t] = a;
    }
    __syncthreads();

    if (t < 8) {
        int b = b0 + t;
        float v[4];
#pragma unroll
        for (int j = 0; j < 4; j++) v[j] = sL[t * 4 + j];
        int i0 = 0;
#pragma unroll
        for (int j = 1; j < 4; j++) if (v[j] > v[i0]) i0 = j;
        int i1 = (i0 == 0) ? 1 : 0;
#pragma unroll
        for (int j = 0; j < 4; j++) if (j != i0 && v[j] > v[i1]) i1 = j;
        float m  = fmaxf(v[i0], v[i1]);
        float e0 = __expf(v[i0] - m), e1 = __expf(v[i1] - m);
        float inv = 1.f / (e0 + e1);
        float w0 = e0 * inv, w1 = e1 * inv;
        d_eidx[2 * b]     = i0;
        d_eidx[2 * b + 1] = i1;
        d_gw[2 * b]       = w0;
        d_gw[2 * b + 1]   = w1;
        d_biasc[b]        = w0 * expb2[i0] + w1 * expb2[i1];
    }
}

// ---------------------------------------------------------
// Stage E: U = gfeat @ expW1[:, :306, :] + b1. Grid (32, 2), 256 thr.
// ---------------------------------------------------------
__global__ void stageE(const float* __restrict__ eW1, const float* __restrict__ eb1)
{
    __shared__ __align__(16) float sA[8 * 308];
    const int t = threadIdx.x;
    int r0 = blockIdx.x * 8;
    int e = blockIdx.y * 2 + (t >> 7);
    int h = t & 127;
    lin_tile<8>(d_gfeat, GLOBAL_, GLOBAL_, 308, B_, r0,
                eW1 + (size_t)e * EXPIN * H_, H_, h,
                eb1[e * H_ + h], true,
                d_U, E_ * H_, e * H_ + h, nullptr, 0, 0, false, sA);
}

// ---------------------------------------------------------
// Combine: pred[b,g] = sum_{e in top2(b)} gw[e]*(sum_h relu(U+V)*W2) + biasc
// ---------------------------------------------------------
__global__ void combine_kernel(const float* __restrict__ expW2,
                               float* __restrict__ pred)
{
    __shared__ float4 sV[16 * 128];      // 16 genes x 512 floats
    __shared__ float  sOut[16][17];
    const int g0   = blockIdx.x * 16;
    const int warp = threadIdx.x >> 5;
    const int lane = threadIdx.x & 31;
    const int b    = blockIdx.y * 16 + warp;
    const int nG   = (G_ - g0) < 16 ? (G_ - g0) : 16;

    const float4* V4 = reinterpret_cast<const float4*>(d_V);
    for (int i = threadIdx.x; i < nG * 128; i += blockDim.x)
        sV[i] = V4[g0 * 128 + i];
    __syncthreads();

    const int   e0  = d_eidx[2 * b], e1 = d_eidx[2 * b + 1];
    const float gw0 = d_gw[2 * b],   gw1 = d_gw[2 * b + 1];
    const float bc  = d_biasc[b];

    const float4* U4 = reinterpret_cast<const float4*>(d_U) + b * 128;
    const float4 u0  = U4[e0 * 32 + lane];
    const float4 u1  = U4[e1 * 32 + lane];
    const float4* W4 = reinterpret_cast<const float4*>(expW2);
    const float4 w20 = W4[e0 * 32 + lane];
    const float4 w21 = W4[e1 * 32 + lane];

    for (int gi = 0; gi < nG; gi++) {
        float4 v = sV[gi * 128 + e0 * 32 + lane];
        float t0 =           fmaxf(u0.x + v.x, 0.f) * w20.x;
        t0 = fmaf(fmaxf(u0.y + v.y, 0.f), w20.y, t0);
        t0 = fmaf(fmaxf(u0.z + v.z, 0.f), w20.z, t0);
        t0 = fmaf(fmaxf(u0.w + v.w, 0.f), w20.w, t0);
        v = sV[gi * 128 + e1 * 32 + lane];
        float t1 =           fmaxf(u1.x + v.x, 0.f) * w21.x;
        t1 = fmaf(fmaxf(u1.y + v.y, 0.f), w21.y, t1);
        t1 = fmaf(fmaxf(u1.z + v.z, 0.f), w21.z, t1);
        t1 = fmaf(fmaxf(u1.w + v.w, 0.f), w21.w, t1);
        float p = gw0 * t0 + gw1 * t1;
#pragma unroll
        for (int o = 16; o; o >>= 1)
            p += __shfl_xor_sync(0xffffffffu, p, o);
        if (lane == 0) sOut[warp][gi] = p + bc;
    }
    __syncwarp();
    if (lane < nG)
        pred[b * G_ + g0 + lane] = sOut[warp][lane];
}

// ---------------------------------------------------------
extern "C" void kernel_launch(void* const* d_in, const int* in_sizes, int n_in,
                              void* d_out, int out_size)
{
    const float* drug_atom = (const float*)d_in[0];
    const float* gex       = (const float*)d_in[1];
    const float* idose     = (const float*)d_in[2];
    const float* cW1 = (const float*)d_in[3];  const float* cb1 = (const float*)d_in[4];
    const float* cW2 = (const float*)d_in[5];  const float* cb2 = (const float*)d_in[6];
    const float* cW3 = (const float*)d_in[7];  const float* cb3 = (const float*)d_in[8];
    const float* dW1 = (const float*)d_in[9];  const float* db1 = (const float*)d_in[10];
    const float* dW2 = (const float*)d_in[11]; const float* db2 = (const float*)d_in[12];
    const float* gene_emb = (const float*)d_in[13];
    const float* gW1 = (const float*)d_in[14]; const float* gb1 = (const float*)d_in[15];
    const float* gW2 = (const float*)d_in[16]; const float* gb2 = (const float*)d_in[17];
    const float* eW1 = (const float*)d_in[18]; const float* eb1 = (const float*)d_in[19];
    const float* eW2 = (const float*)d_in[20]; const float* eb2 = (const float*)d_in[21];

    float* pred = (float*)d_out;
    float* cellOut = (out_size >= B_ * G_ + B_ * DCELL) ? pred + B_ * G_ : nullptr;

    // A: drug sum + cell L1 + dose L1 + V   (input-only, fused)
    stageA<<<470, 256>>>(drug_atom, gex, cW1, cb1, idose, dW1, db1, gene_emb, eW1);
    // B: cell L2 + dose L2
    stageB<<<64, 256>>>(cW2, cb2, dW2, db2);
    // C: cell L3 (also emits cell output)
    stageC<<<32, 256>>>(cW3, cb3, cellOut);
    // D: gating
    stageD<<<32, 128>>>(gW1, gb1, gW2, gb2, eb2);
    // E: U
    stageE<<<dim3(32, 2), 256>>>(eW1, eb1);
    // F: combine
    dim3 cg((G_ + 15) / 16, B_ / 16);
    combine_kernel<<<cg, 512>>>(eW2, pred);
}

// round 3
// speedup vs baseline: 7.7670x; 1.8805x over previous
#include <cuda_runtime.h>
#include <cuda_bf16.h>
#include <math.h>

#define B_   256
#define A_   64
#define G_   978
#define DDRUG 128
#define DCELL 50
#define CELLIN 978
#define DOSEIN 12
#define GLOBAL_ 306   // 128+50+128
#define EXPIN 434
#define E_   4
#define H_   128

#define NCHUNK 8      // k-split for cell L1

// -------- device scratch --------
__device__ float d_gfeat[B_ * GLOBAL_];
__device__ float d_c1p[NCHUNK * B_ * 200];  // cell L1 partials [chunk][row][200]
__device__ float d_d1[B_ * 64];
__device__ float d_U[B_ * E_ * H_];         // [b][e*128+h]
__device__ float d_V[G_ * E_ * H_];         // [g][e*128+h]
__device__ int   d_eidx[B_ * 2];
__device__ float d_gw[B_ * 2];
__device__ float d_biasc[B_];

// =========================================================
// Stage A (inputs only), 256 threads, grid partition:
//   [0,128)        drug atom-sum, 2 rows/block
//   [128,384)      cell L1 partials: 8 k-chunks x 32 row-tiles (RB=8)
//   [384,448)      dose L1: 4 rows x 64 cols per block
//   [448,694)      V = gene_emb @ eW1[:,306:,:]: 123 row-tiles x 2 expert-pairs
// =========================================================
__global__ void __launch_bounds__(256) stageA(
    const float* __restrict__ drug,
    const float* __restrict__ gex,
    const float* __restrict__ cW1,
    const float* __restrict__ idose,
    const float* __restrict__ dW1, const float* __restrict__ db1,
    const float* __restrict__ gene_emb,
    const float* __restrict__ eW1)
{
    __shared__ __align__(16) float sA[8 * 128];   // max tile: 8x124 / 8x128
    const int blk = blockIdx.x;
    const int t = threadIdx.x;

    if (blk < 128) {
        // ---- drug sum ----
        int b = blk * 2 + (t >> 7);
        int d = t & 127;
        const float* p = drug + (size_t)b * A_ * DDRUG + d;
        float s = 0.f;
#pragma unroll
        for (int a = 0; a < A_; a++) s += p[a * DDRUG];
        d_gfeat[b * GLOBAL_ + d] = s;

    } else if (blk < 384) {
        // ---- cell L1 partial: chunk c, rows r0..r0+7 ----
        int idx = blk - 128;
        int c = idx >> 5, rt = idx & 31;
        int r0 = rt * 8;
        int k0 = (CELLIN * c) / NCHUNK;
        int k1 = (CELLIN * (c + 1)) / NCHUNK;
        int kc = k1 - k0;                 // 122 or 123
        const int Kp = 124;
        for (int i = t; i < 8 * Kp; i += 256) {
            int r = i / Kp, k = i - r * Kp;
            sA[i] = (k < kc) ? gex[(r0 + r) * CELLIN + k0 + k] : 0.f;
        }
        __syncthreads();
        if (t < 200) {
            float acc[8];
#pragma unroll
            for (int r = 0; r < 8; r++) acc[r] = 0.f;
            int kc4 = kc & ~3;
            for (int k = 0; k < kc4; k += 4) {
                float w0 = cW1[(k0 + k + 0) * 200 + t];
                float w1 = cW1[(k0 + k + 1) * 200 + t];
                float w2 = cW1[(k0 + k + 2) * 200 + t];
                float w3 = cW1[(k0 + k + 3) * 200 + t];
#pragma unroll
                for (int r = 0; r < 8; r++) {
                    float4 x = *reinterpret_cast<const float4*>(sA + r * Kp + k);
                    acc[r] = fmaf(x.x, w0, acc[r]);
                    acc[r] = fmaf(x.y, w1, acc[r]);
                    acc[r] = fmaf(x.z, w2, acc[r]);
                    acc[r] = fmaf(x.w, w3, acc[r]);
                }
            }
            for (int k = kc4; k < kc; k++) {
                float w = cW1[(k0 + k) * 200 + t];
#pragma unroll
                for (int r = 0; r < 8; r++)
                    acc[r] = fmaf(sA[r * Kp + k], w, acc[r]);
            }
#pragma unroll
            for (int r = 0; r < 8; r++)
                d_c1p[(c * B_ + r0 + r) * 200 + t] = acc[r];
        }

    } else if (blk < 448) {
        // ---- dose L1 ----
        int row = (blk - 384) * 4 + (t >> 6);
        int col = t & 63;
        float a = db1[col];
        const float* x = idose + row * DOSEIN;
#pragma unroll
        for (int k = 0; k < DOSEIN; k++)
            a = fmaf(x[k], dW1[k * 64 + col], a);
        d_d1[row * 64 + col] = fmaxf(a, 0.f);

    } else {
        // ---- V: 8 genes x 2 experts ----
        int idx = blk - 448;             // 0..245
        int rt = idx >> 1, ep = idx & 1;
        int r0 = rt * 8;
        int e = ep * 2 + (t >> 7), h = t & 127;
        for (int i = t; i < 8 * 128; i += 256) {
            int r = i >> 7, k = i & 127;
            sA[i] = (r0 + r < G_) ? gene_emb[(r0 + r) * 128 + k] : 0.f;
        }
        __syncthreads();
        float acc[8];
#pragma unroll
        for (int r = 0; r < 8; r++) acc[r] = 0.f;
        const float* Wv = eW1 + (size_t)e * EXPIN * H_ + (size_t)GLOBAL_ * H_ + h;
#pragma unroll 1
        for (int k = 0; k < 128; k += 4) {
            float w0 = Wv[(k + 0) * H_];
            float w1 = Wv[(k + 1) * H_];
            float w2 = Wv[(k + 2) * H_];
            float w3 = Wv[(k + 3) * H_];
#pragma unroll
            for (int r = 0; r < 8; r++) {
                float4 x = *reinterpret_cast<const float4*>(sA + r * 128 + k);
                acc[r] = fmaf(x.x, w0, acc[r]);
                acc[r] = fmaf(x.y, w1, acc[r]);
                acc[r] = fmaf(x.z, w2, acc[r]);
                acc[r] = fmaf(x.w, w3, acc[r]);
            }
        }
#pragma unroll
        for (int r = 0; r < 8; r++)
            if (r0 + r < G_) d_V[(r0 + r) * (E_ * H_) + e * H_ + h] = acc[r];
    }
}

// =========================================================
// Stage BC, 256 threads:
//   [0,64)   cell L2+L3 fused, 4 rows/block (reduce L1 partials in smem)
//   [64,128) dose L2, 4 rows/block
// =========================================================
__global__ void __launch_bounds__(256) stageBC(
    const float* __restrict__ cb1,
    const float* __restrict__ cW2, const float* __restrict__ cb2,
    const float* __restrict__ cW3, const float* __restrict__ cb3,
    const float* __restrict__ dW2, const float* __restrict__ db2,
    float* __restrict__ cellOut)
{
    __shared__ __align__(16) float sA[4 * 200];
    __shared__ __align__(16) float sH[4 * 100];
    const int blk = blockIdx.x;
    const int t = threadIdx.x;

    if (blk < 64) {
        int r0 = blk * 4;
        // reduce L1 partials + bias + relu -> sA[4][200]
        for (int i = t; i < 4 * 200; i += 256) {
            int r = i / 200, k = i - r * 200;
            float s = cb1[k];
#pragma unroll
            for (int c = 0; c < NCHUNK; c++)
                s += d_c1p[(c * B_ + r0 + r) * 200 + k];
            sA[i] = fmaxf(s, 0.f);
        }
        __syncthreads();
        // L2: 200 -> 100
        if (t < 100) {
            float acc[4];
#pragma unroll
            for (int r = 0; r < 4; r++) acc[r] = cb2[t];
            for (int k = 0; k < 200; k += 4) {
                float w0 = cW2[(k + 0) * 100 + t];
                float w1 = cW2[(k + 1) * 100 + t];
                float w2 = cW2[(k + 2) * 100 + t];
                float w3 = cW2[(k + 3) * 100 + t];
#pragma unroll
                for (int r = 0; r < 4; r++) {
                    float4 x = *reinterpret_cast<const float4*>(sA + r * 200 + k);
                    acc[r] = fmaf(x.x, w0, acc[r]);
                    acc[r] = fmaf(x.y, w1, acc[r]);
                    acc[r] = fmaf(x.z, w2, acc[r]);
                    acc[r] = fmaf(x.w, w3, acc[r]);
                }
            }
#pragma unroll
            for (int r = 0; r < 4; r++)
                sH[r * 100 + t] = fmaxf(acc[r], 0.f);
        }
        __syncthreads();
        // L3: 100 -> 50
        if (t < 50) {
            float acc[4];
#pragma unroll
            for (int r = 0; r < 4; r++) acc[r] = cb3[t];
            for (int k = 0; k < 100; k += 4) {
                float w0 = cW3[(k + 0) * 50 + t];
                float w1 = cW3[(k + 1) * 50 + t];
                float w2 = cW3[(k + 2) * 50 + t];
                float w3 = cW3[(k + 3) * 50 + t];
#pragma unroll
                for (int r = 0; r < 4; r++) {
                    float4 x = *reinterpret_cast<const float4*>(sH + r * 100 + k);
                    acc[r] = fmaf(x.x, w0, acc[r]);
                    acc[r] = fmaf(x.y, w1, acc[r]);
                    acc[r] = fmaf(x.z, w2, acc[r]);
                    acc[r] = fmaf(x.w, w3, acc[r]);
                }
            }
#pragma unroll
            for (int r = 0; r < 4; r++) {
                float v = fmaxf(acc[r], 0.f);
                d_gfeat[(r0 + r) * GLOBAL_ + 128 + t] = v;
                if (cellOut) cellOut[(r0 + r) * DCELL + t] = v;
            }
        }
    } else {
        // dose L2: 64 -> 128
        int r0 = (blk - 64) * 4;
        for (int i = t; i < 4 * 64; i += 256) {
            int r = i >> 6, k = i & 63;
            sA[i] = d_d1[(r0 + r) * 64 + k];
        }
        __syncthreads();
        if (t < 128) {
            float acc[4];
#pragma unroll
            for (int r = 0; r < 4; r++) acc[r] = db2[t];
#pragma unroll 4
            for (int k = 0; k < 64; k += 4) {
                float w0 = dW2[(k + 0) * 128 + t];
                float w1 = dW2[(k + 1) * 128 + t];
                float w2 = dW2[(k + 2) * 128 + t];
                float w3 = dW2[(k + 3) * 128 + t];
#pragma unroll
                for (int r = 0; r < 4; r++) {
                    float4 x = *reinterpret_cast<const float4*>(sA + r * 64 + k);
                    acc[r] = fmaf(x.x, w0, acc[r]);
                    acc[r] = fmaf(x.y, w1, acc[r]);
                    acc[r] = fmaf(x.z, w2, acc[r]);
                    acc[r] = fmaf(x.w, w3, acc[r]);
                }
            }
#pragma unroll
            for (int r = 0; r < 4; r++)
                d_gfeat[(r0 + r) * GLOBAL_ + 178 + t] = fmaxf(acc[r], 0.f);
        }
    }
}

// =========================================================
// Stage DE, 256 threads (gate and U both depend only on gfeat):
//   [0,64)   gating: 4 rows/block, hidden GEMM k-split in half
//   [64,128) U: 8 rows x 2 experts per block
// =========================================================
__global__ void __launch_bounds__(256) stageDE(
    const float* __restrict__ gW1, const float* __restrict__ gb1,
    const float* __restrict__ gW2, const float* __restrict__ gb2,
    const float* __restrict__ eW1, const float* __restrict__ eb1,
    const float* __restrict__ eb2)
{
    __shared__ __align__(16) float sG[8 * 308];
    const int blk = blockIdx.x;
    const int t = threadIdx.x;

    if (blk < 64) {
        __shared__ float sHp[2][4][128];
        __shared__ float sH[4 * 128];
        __shared__ float sL[16];
        int b0 = blk * 4;
        for (int i = t; i < 4 * 308; i += 256) {
            int r = i / 308, k = i - r * 308;
            sG[i] = (k < GLOBAL_) ? d_gfeat[(b0 + r) * GLOBAL_ + k] : 0.f;
        }
        __syncthreads();
        {   // hidden: k halves [0,152) and [152,306) (+2 pad zeros in second)
            int half = t >> 7, h = t & 127;
            int kA = half * 152, kB = half ? 308 : 152;
            float acc[4] = {0.f, 0.f, 0.f, 0.f};
            for (int k = kA; k < kB; k += 4) {
                float w0 = (k + 0 < GLOBAL_) ? gW1[(k + 0) * 128 + h] : 0.f;
                float w1 = (k + 1 < GLOBAL_) ? gW1[(k + 1) * 128 + h] : 0.f;
                float w2 = (k + 2 < GLOBAL_) ? gW1[(k + 2) * 128 + h] : 0.f;
                float w3 = (k + 3 < GLOBAL_) ? gW1[(k + 3) * 128 + h] : 0.f;
#pragma unroll
                for (int r = 0; r < 4; r++) {
                    float4 x = *reinterpret_cast<const float4*>(sG + r * 308 + k);
                    acc[r] = fmaf(x.x, w0, acc[r]);
                    acc[r] = fmaf(x.y, w1, acc[r]);
                    acc[r] = fmaf(x.z, w2, acc[r]);
                    acc[r] = fmaf(x.w, w3, acc[r]);
                }
            }
#pragma unroll
            for (int r = 0; r < 4; r++) sHp[half][r][h] = acc[r];
        }
        __syncthreads();
        if (t < 128) {
            float bb = gb1[t];
#pragma unroll
            for (int r = 0; r < 4; r++)
                sH[r * 128 + t] = fmaxf(sHp[0][r][t] + sHp[1][r][t] + bb, 0.f);
        }
        __syncthreads();
        if (t < 16) {
            int r = t >> 2, e = t & 3;
            float a = gb2[e];
            for (int k = 0; k < 128; k++)
                a = fmaf(sH[r * 128 + k], gW2[k * 4 + e], a);
            sL[t] = a;
        }
        __syncthreads();
        if (t < 4) {
            int b = b0 + t;
            float v[4];
#pragma unroll
            for (int j = 0; j < 4; j++) v[j] = sL[t * 4 + j];
            int i0 = 0;
#pragma unroll
            for (int j = 1; j < 4; j++) if (v[j] > v[i0]) i0 = j;
            int i1 = (i0 == 0) ? 1 : 0;
#pragma unroll
            for (int j = 0; j < 4; j++) if (j != i0 && v[j] > v[i1]) i1 = j;
            float m  = fmaxf(v[i0], v[i1]);
            float e0 = __expf(v[i0] - m), e1 = __expf(v[i1] - m);
            float inv = 1.f / (e0 + e1);
            float w0 = e0 * inv, w1 = e1 * inv;
            d_eidx[2 * b]     = i0;
            d_eidx[2 * b + 1] = i1;
            d_gw[2 * b]       = w0;
            d_gw[2 * b + 1]   = w1;
            d_biasc[b]        = w0 * eb2[i0] + w1 * eb2[i1];
        }
    } else {
        // U: rows r0..r0+7, experts ep*2 + (t>>7)
        int idx = blk - 64;
        int rt = idx >> 1, ep = idx & 1;
        int r0 = rt * 8;
        int e = ep * 2 + (t >> 7), h = t & 127;
        for (int i = t; i < 8 * 308; i += 256) {
            int r = i / 308, k = i - r * 308;
            sG[i] = (k < GLOBAL_) ? d_gfeat[(r0 + r) * GLOBAL_ + k] : 0.f;
        }
        __syncthreads();
        float acc[8];
        float bb = eb1[e * H_ + h];
#pragma unroll
        for (int r = 0; r < 8; r++) acc[r] = bb;
        const float* Wp = eW1 + (size_t)e * EXPIN * H_ + h;
#pragma unroll 1
        for (int k = 0; k < 308; k += 4) {
            float w0 = (k + 0 < GLOBAL_) ? Wp[(k + 0) * H_] : 0.f;
            float w1 = (k + 1 < GLOBAL_) ? Wp[(k + 1) * H_] : 0.f;
            float w2 = (k + 2 < GLOBAL_) ? Wp[(k + 2) * H_] : 0.f;
            float w3 = (k + 3 < GLOBAL_) ? Wp[(k + 3) * H_] : 0.f;
#pragma unroll
            for (int r = 0; r < 8; r++) {
                float4 x = *reinterpret_cast<const float4*>(sG + r * 308 + k);
                acc[r] = fmaf(x.x, w0, acc[r]);
                acc[r] = fmaf(x.y, w1, acc[r]);
                acc[r] = fmaf(x.z, w2, acc[r]);
                acc[r] = fmaf(x.w, w3, acc[r]);
            }
        }
#pragma unroll
        for (int r = 0; r < 8; r++)
            d_U[(r0 + r) * (E_ * H_) + e * H_ + h] = acc[r];
    }
}

// =========================================================
// Combine: pred[b,g] = sum_{e in top2(b)} gw*(sum_h relu(U+V)*W2) + biasc
// 16 warps (one b each), 16-gene V tile in smem.
// =========================================================
__global__ void __launch_bounds__(512) combine_kernel(
    const float* __restrict__ expW2, float* __restrict__ pred)
{
    __shared__ float4 sV[16 * 128];
    __shared__ float  sOut[16][17];
    const int g0   = blockIdx.x * 16;
    const int warp = threadIdx.x >> 5;
    const int lane = threadIdx.x & 31;
    const int b    = blockIdx.y * 16 + warp;
    const int nG   = (G_ - g0) < 16 ? (G_ - g0) : 16;

    const float4* V4 = reinterpret_cast<const float4*>(d_V);
    for (int i = threadIdx.x; i < nG * 128; i += blockDim.x)
        sV[i] = V4[g0 * 128 + i];
    __syncthreads();

    const int   e0  = d_eidx[2 * b], e1 = d_eidx[2 * b + 1];
    const float gw0 = d_gw[2 * b],   gw1 = d_gw[2 * b + 1];
    const float bc  = d_biasc[b];

    const float4* U4 = reinterpret_cast<const float4*>(d_U) + b * 128;
    const float4 u0  = U4[e0 * 32 + lane];
    const float4 u1  = U4[e1 * 32 + lane];
    const float4* W4 = reinterpret_cast<const float4*>(expW2);
    const float4 w20 = W4[e0 * 32 + lane];
    const float4 w21 = W4[e1 * 32 + lane];

    for (int gi = 0; gi < nG; gi++) {
        float4 v = sV[gi * 128 + e0 * 32 + lane];
        float t0 =           fmaxf(u0.x + v.x, 0.f) * w20.x;
        t0 = fmaf(fmaxf(u0.y + v.y, 0.f), w20.y, t0);
        t0 = fmaf(fmaxf(u0.z + v.z, 0.f), w20.z, t0);
        t0 = fmaf(fmaxf(u0.w + v.w, 0.f), w20.w, t0);
        v = sV[gi * 128 + e1 * 32 + lane];
        float t1 =           fmaxf(u1.x + v.x, 0.f) * w21.x;
        t1 = fmaf(fmaxf(u1.y + v.y, 0.f), w21.y, t1);
        t1 = fmaf(fmaxf(u1.z + v.z, 0.f), w21.z, t1);
        t1 = fmaf(fmaxf(u1.w + v.w, 0.f), w21.w, t1);
        float p = gw0 * t0 + gw1 * t1;
#pragma unroll
        for (int o = 16; o; o >>= 1)
            p += __shfl_xor_sync(0xffffffffu, p, o);
        if (lane == 0) sOut[warp][gi] = p + bc;
    }
    __syncwarp();
    if (lane < nG)
        pred[b * G_ + g0 + lane] = sOut[warp][lane];
}

// =========================================================
extern "C" void kernel_launch(void* const* d_in, const int* in_sizes, int n_in,
                              void* d_out, int out_size)
{
    const float* drug_atom = (const float*)d_in[0];
    const float* gex       = (const float*)d_in[1];
    const float* idose     = (const float*)d_in[2];
    const float* cW1 = (const float*)d_in[3];  const float* cb1 = (const float*)d_in[4];
    const float* cW2 = (const float*)d_in[5];  const float* cb2 = (const float*)d_in[6];
    const float* cW3 = (const float*)d_in[7];  const float* cb3 = (const float*)d_in[8];
    const float* dW1 = (const float*)d_in[9];  const float* db1 = (const float*)d_in[10];
    const float* dW2 = (const float*)d_in[11]; const float* db2 = (const float*)d_in[12];
    const float* gene_emb = (const float*)d_in[13];
    const float* gW1 = (const float*)d_in[14]; const float* gb1 = (const float*)d_in[15];
    const float* gW2 = (const float*)d_in[16]; const float* gb2 = (const float*)d_in[17];
    const float* eW1 = (const float*)d_in[18]; const float* eb1 = (const float*)d_in[19];
    const float* eW2 = (const float*)d_in[20]; const float* eb2 = (const float*)d_in[21];

    float* pred = (float*)d_out;
    float* cellOut = (out_size >= B_ * G_ + B_ * DCELL) ? pred + B_ * G_ : nullptr;

    stageA<<<694, 256>>>(drug_atom, gex, cW1, idose, dW1, db1, gene_emb, eW1);
    stageBC<<<128, 256>>>(cb1, cW2, cb2, cW3, cb3, dW2, db2, cellOut);
    stageDE<<<128, 256>>>(gW1, gb1, gW2, gb2, eW1, eb1, eb2);
    dim3 cg((G_ + 15) / 16, B_ / 16);
    combine_kernel<<<cg, 512>>>(eW2, pred);
}